// round 15
// baseline (speedup 1.0000x reference)
#include <cuda_runtime.h>
#include <cstdint>
#include <cstddef>

// Problem constants
#define TB_   128
#define NSEQ  196
#define CDIM  512
#define HDIM  2048
#define TSTEP 4
#define BB    32
#define MROWS (TB_*NSEQ)          // 25088
#define SLAB1 (NSEQ*HDIM)         // 401408
#define SLAB2 (NSEQ*CDIM)         // 100352
#define NWORD 64                  // 2048 bits per GEMM2 row

// ---------------- scratch (device globals) ---------------------------------
__device__ float    g_h1[(size_t)MROWS*HDIM];   // GEMM1 out (tb*196+n, h)
__device__ float    g_o2[(size_t)MROWS*CDIM];   // GEMM2 out (tb*196+j, c)
__device__ uint32_t g_mask[(size_t)MROWS*NWORD]; // spike bitmask per GEMM2 row
__device__ float    g_w2T[(size_t)HDIM*CDIM];   // w2 transposed [k][c]
__device__ float    g_xT [(size_t)CDIM*MROWS];  // x transposed  [k][m]
__device__ float    g_w1T[(size_t)CDIM*HDIM];   // w1 transposed [k][h]
__device__ double   g_sum1[HDIM], g_sq1[HDIM];
__device__ double   g_sum2[CDIM], g_sq2[CDIM];
__device__ float    g_mean1[HDIM], g_rstd1[HDIM];
__device__ float    g_mean2[CDIM], g_rstd2[CDIM];

// ---------------- PTX helpers ----------------------------------------------
__device__ __forceinline__ uint32_t smem_u32(const void* p) {
    uint32_t a;
    asm("{ .reg .u64 t; cvta.to.shared.u64 t, %1; cvt.u32.u64 %0, t; }" : "=r"(a) : "l"(p));
    return a;
}
#define CP_ASYNC16(dst, src) \
    asm volatile("cp.async.cg.shared.global [%0], [%1], 16;" :: "r"(dst), "l"(src))
#define CP_COMMIT() asm volatile("cp.async.commit_group;")
#define CP_WAIT(n)  asm volatile("cp.async.wait_group %0;" :: "n"(n))

__device__ __forceinline__ void ffma2(unsigned long long &d,
                                      unsigned long long a,
                                      unsigned long long b)
{
    asm("fma.rn.f32x2 %0, %1, %2, %3;" : "=l"(d) : "l"(a), "l"(b), "l"(d));
}
__device__ __forceinline__ unsigned long long dup2(float v)
{
    unsigned long long r;
    asm("mov.b64 %0, {%1, %1};" : "=l"(r) : "f"(v));
    return r;
}
union U2F { unsigned long long u; float2 f; };

// ---------------- zero stats + mask (single kernel) -------------------------
__global__ void zero_all_kernel() {
    size_t i = (size_t)blockIdx.x * blockDim.x + threadIdx.x;
    if (i < HDIM) { g_sum1[i] = 0.0; g_sq1[i] = 0.0; }
    if (i < CDIM) { g_sum2[i] = 0.0; g_sq2[i] = 0.0; }
    if (i < (size_t)MROWS * NWORD) g_mask[i] = 0u;
}

// ---------------- generic 32x32 tile transpose: dst[c][r] = src[r][c] ------
__global__ void transpose_rc_kernel(const float* __restrict__ src,
                                    float* __restrict__ dst, int R, int C)
{
    __shared__ float t[32][33];
    int r0 = blockIdx.x * 32, c0 = blockIdx.y * 32;
    int x = threadIdx.x, y = threadIdx.y;     // block (32,8)
#pragma unroll
    for (int yy = y; yy < 32; yy += 8)
        t[yy][x] = src[(size_t)(r0 + yy) * C + c0 + x];
    __syncthreads();
#pragma unroll
    for (int yy = y; yy < 32; yy += 8)
        dst[(size_t)(c0 + yy) * R + r0 + x] = t[x][yy];
}

// ---------------- GEMM1: 3-stage cp.async ring + f32x2 + fused BN1 stats ---
// C[M,H] = x[M,512] * w1[H,512]^T, bitwise == ascending-k FMA chain.
// Epilogue: per-column fp32 partials -> smem reduce -> double atomics.
#define BM 128
#define BN 128
#define BK 16
#define NIT (CDIM / BK)   // 32

__global__ __launch_bounds__(256, 2)
void sgemm1_kernel()
{
    __shared__ __align__(16) float As[3][BK][BM];   // 24 KB (reused in epilogue)
    __shared__ __align__(16) float Bs[3][BK][BN];   // 24 KB

    const int tid = threadIdx.x;
    const int m0 = blockIdx.y * BM;
    const int n0 = blockIdx.x * BN;
    const int tx = tid & 15;
    const int ty = tid >> 4;

    unsigned long long acc[8][4];
#pragma unroll
    for (int i = 0; i < 8; i++)
#pragma unroll
        for (int p = 0; p < 4; p++) acc[i][p] = 0ull;

    const int ck = tid >> 5;
    const int cc = (tid & 31) * 4;

    auto load_stage = [&](int s, int k0) {
#pragma unroll
        for (int i = 0; i < 2; i++) {
            int k = ck + i * 8;
            CP_ASYNC16(smem_u32(&As[s][k][cc]),
                       g_xT + (size_t)(k0 + k) * MROWS + m0 + cc);
        }
#pragma unroll
        for (int i = 0; i < 2; i++) {
            int k = ck + i * 8;
            CP_ASYNC16(smem_u32(&Bs[s][k][cc]),
                       g_w1T + (size_t)(k0 + k) * HDIM + n0 + cc);
        }
        CP_COMMIT();
    };

    load_stage(0, 0);
    load_stage(1, BK);

    for (int it = 0; it < NIT; it++) {
        const int cur = it % 3;
        if (it + 1 < NIT) CP_WAIT(1);
        else              CP_WAIT(0);
        __syncthreads();

#pragma unroll
        for (int k = 0; k < BK; k++) {
            float4 af0 = *(const float4*)&As[cur][k][ty * 8];
            float4 af1 = *(const float4*)&As[cur][k][ty * 8 + 4];
            unsigned long long a2[8];
            a2[0] = dup2(af0.x); a2[1] = dup2(af0.y);
            a2[2] = dup2(af0.z); a2[3] = dup2(af0.w);
            a2[4] = dup2(af1.x); a2[5] = dup2(af1.y);
            a2[6] = dup2(af1.z); a2[7] = dup2(af1.w);
            ulonglong2 bq0 = *(const ulonglong2*)&Bs[cur][k][tx * 8];
            ulonglong2 bq1 = *(const ulonglong2*)&Bs[cur][k][tx * 8 + 4];
            unsigned long long b2[4] = {bq0.x, bq0.y, bq1.x, bq1.y};
#pragma unroll
            for (int i = 0; i < 8; i++)
#pragma unroll
                for (int p = 0; p < 4; p++)
                    ffma2(acc[i][p], a2[i], b2[p]);
        }

        if (it + 2 < NIT)
            load_stage((it + 2) % 3, (it + 2) * BK);
    }

    // ---- write C ----
#pragma unroll
    for (int i = 0; i < 8; i++) {
        int r = m0 + ty * 8 + i;
        float* cr = g_h1 + (size_t)r * HDIM + n0 + tx * 8;
        ulonglong2 v0; v0.x = acc[i][0]; v0.y = acc[i][1];
        ulonglong2 v1; v1.x = acc[i][2]; v1.y = acc[i][3];
        *(ulonglong2*)(cr)     = v0;
        *(ulonglong2*)(cr + 4) = v1;
    }

    // ---- fused BN1 stats: per-thread column partials over 8 rows ----
    float cs[8], cq[8];
#pragma unroll
    for (int q = 0; q < 8; q++) { cs[q] = 0.f; cq[q] = 0.f; }
#pragma unroll
    for (int i = 0; i < 8; i++) {
#pragma unroll
        for (int p = 0; p < 4; p++) {
            U2F u; u.u = acc[i][p];
            cs[2*p]   += u.f.x; cq[2*p]   = fmaf(u.f.x, u.f.x, cq[2*p]);
            cs[2*p+1] += u.f.y; cq[2*p+1] = fmaf(u.f.y, u.f.y, cq[2*p+1]);
        }
    }
    __syncthreads();   // done reading As/Bs; safe to reuse As as reduce buffer
    float* ssum = &As[0][0][0];         // 128 cols x 17 stride = 2176 floats
    float* ssq  = ssum + 2176;          // total 17408 B < 24 KB
#pragma unroll
    for (int q = 0; q < 8; q++) {
        ssum[(tx * 8 + q) * 17 + ty] = cs[q];
        ssq [(tx * 8 + q) * 17 + ty] = cq[q];
    }
    __syncthreads();
    if (tid < 128) {
        double ds = 0.0, dq = 0.0;
#pragma unroll
        for (int t2 = 0; t2 < 16; t2++) {
            ds += (double)ssum[tid * 17 + t2];
            dq += (double)ssq [tid * 17 + t2];
        }
        atomicAdd(&g_sum1[n0 + tid], ds);
        atomicAdd(&g_sq1 [n0 + tid], dq);
    }
}

// ---------------- BN stats (layer 2 only) / final --------------------------
__global__ __launch_bounds__(256)
void bn_stats2_kernel()
{
    constexpr int CH  = CDIM;
    constexpr int PER = CH / 256;
    float s[PER], q[PER];
#pragma unroll
    for (int j = 0; j < PER; j++) { s[j] = 0.f; q[j] = 0.f; }
    const int c0 = threadIdx.x;
    const float* base = g_o2 + (size_t)blockIdx.x * 128 * CH;
    for (int r = 0; r < 128; r++) {
        const float* row = base + (size_t)r * CH;
#pragma unroll
        for (int j = 0; j < PER; j++) {
            float v = row[c0 + j * 256];
            s[j] += v;
            q[j] = fmaf(v, v, q[j]);
        }
    }
#pragma unroll
    for (int j = 0; j < PER; j++) {
        atomicAdd(&g_sum2[c0 + j * 256], (double)s[j]);
        atomicAdd(&g_sq2 [c0 + j * 256], (double)q[j]);
    }
}

template<bool SECOND>
__global__ void bn_final_kernel()
{
    constexpr int CH = SECOND ? CDIM : HDIM;
    const double* SUM = SECOND ? g_sum2 : g_sum1;
    const double* SQ  = SECOND ? g_sq2  : g_sq1;
    float* MEAN = SECOND ? g_mean2 : g_mean1;
    float* RSTD = SECOND ? g_rstd2 : g_rstd1;
    int c = blockIdx.x * blockDim.x + threadIdx.x;
    if (c < CH) {
        const double inv_n = 1.0 / (double)MROWS;
        double m   = SUM[c] * inv_n;
        double var = SQ[c] * inv_n - m * m;
        MEAN[c] = (float)m;
        RSTD[c] = rsqrtf((float)var + 1e-5f);
    }
}

// ---------------- LIF layer 1 -> spike bitmask (UNCHANGED) -----------------
__global__ __launch_bounds__(256)
void lif1_kernel(const float* __restrict__ gamma, const float* __restrict__ beta)
{
    size_t tid = (size_t)blockIdx.x * blockDim.x + threadIdx.x;
    int c = (int)(tid % HDIM);
    size_t rest = tid / HDIM;
    int n = (int)(rest % NSEQ);
    int b = (int)(rest / NSEQ);

    float m  = g_mean1[c];
    float r  = g_rstd1[c];
    float gm = gamma[c];
    float bt = beta[c];

    int f = n * HDIM + c;
    int k = f / NSEQ;
    int j = f - k * NSEQ;
    uint32_t bit  = 1u << (k & 31);
    int      word = k >> 5;

    float v = 0.f;
#pragma unroll
    for (int t = 0; t < TSTEP; t++) {
        int tb = t * BB + b;
        float x  = g_h1[((size_t)tb * NSEQ + n) * HDIM + c];
        float xn = __fadd_rn(__fmul_rn(__fmul_rn(gm, __fsub_rn(x, m)), r), bt);
        v = __fadd_rn(v, __fmul_rn(__fsub_rn(xn, v), 0.5f));
        if (v >= 1.0f) {
            atomicOr(&g_mask[(size_t)(tb * NSEQ + j) * NWORD + word], bit);
            v = 0.f;
        }
    }
}

// ---------------- sparse GEMM2: 8 rows in parallel, ILP-8 chains -----------
#define RPC 8
__global__ __launch_bounds__(512)
void gemm2_sparse_kernel()
{
    __shared__ uint16_t klist[RPC][HDIM];
    __shared__ int wsum[16];
    __shared__ int knum[RPC];

    const int tid = threadIdx.x;
    const int r   = tid >> 6;          // row slot 0..7
    const int w   = tid & 63;          // mask word
    const int row = blockIdx.x * RPC + r;

    uint32_t mw = g_mask[(size_t)row * NWORD + w];
    int cnt = __popc(mw);
    int incl = cnt;
#pragma unroll
    for (int d = 1; d < 32; d <<= 1) {
        int vv = __shfl_up_sync(0xffffffffu, incl, d);
        if ((tid & 31) >= d) incl += vv;
    }
    if ((tid & 31) == 31) wsum[tid >> 5] = incl;
    __syncthreads();

    int off = incl - cnt + ((w >= 32) ? wsum[r * 2] : 0);
    {
        uint32_t m2 = mw;
        int kb = w * 32;
        while (m2) {
            int b = __ffs(m2) - 1;
            m2 &= m2 - 1;
            klist[r][off++] = (uint16_t)(kb + b);
        }
    }
    if (w == 0) knum[r] = wsum[r * 2] + wsum[r * 2 + 1];
    __syncthreads();

    const int c0 = (tid & 63) * 8;
    const int kn = knum[r];
    float acc[8];
#pragma unroll
    for (int j = 0; j < 8; j++) acc[j] = 0.f;

    int i = 0;
    for (; i + 4 <= kn; i += 4) {
        int k0 = klist[r][i+0], k1 = klist[r][i+1];
        int k2 = klist[r][i+2], k3 = klist[r][i+3];
        const float4* p0 = (const float4*)(g_w2T + (size_t)k0 * CDIM + c0);
        const float4* p1 = (const float4*)(g_w2T + (size_t)k1 * CDIM + c0);
        const float4* p2 = (const float4*)(g_w2T + (size_t)k2 * CDIM + c0);
        const float4* p3 = (const float4*)(g_w2T + (size_t)k3 * CDIM + c0);
        float4 a0 = p0[0], a1 = p0[1];
        float4 b0 = p1[0], b1 = p1[1];
        float4 c0_ = p2[0], c1_ = p2[1];
        float4 d0 = p3[0], d1 = p3[1];
        acc[0] = __fadd_rn(acc[0], a0.x); acc[1] = __fadd_rn(acc[1], a0.y);
        acc[2] = __fadd_rn(acc[2], a0.z); acc[3] = __fadd_rn(acc[3], a0.w);
        acc[4] = __fadd_rn(acc[4], a1.x); acc[5] = __fadd_rn(acc[5], a1.y);
        acc[6] = __fadd_rn(acc[6], a1.z); acc[7] = __fadd_rn(acc[7], a1.w);
        acc[0] = __fadd_rn(acc[0], b0.x); acc[1] = __fadd_rn(acc[1], b0.y);
        acc[2] = __fadd_rn(acc[2], b0.z); acc[3] = __fadd_rn(acc[3], b0.w);
        acc[4] = __fadd_rn(acc[4], b1.x); acc[5] = __fadd_rn(acc[5], b1.y);
        acc[6] = __fadd_rn(acc[6], b1.z); acc[7] = __fadd_rn(acc[7], b1.w);
        acc[0] = __fadd_rn(acc[0], c0_.x); acc[1] = __fadd_rn(acc[1], c0_.y);
        acc[2] = __fadd_rn(acc[2], c0_.z); acc[3] = __fadd_rn(acc[3], c0_.w);
        acc[4] = __fadd_rn(acc[4], c1_.x); acc[5] = __fadd_rn(acc[5], c1_.y);
        acc[6] = __fadd_rn(acc[6], c1_.z); acc[7] = __fadd_rn(acc[7], c1_.w);
        acc[0] = __fadd_rn(acc[0], d0.x); acc[1] = __fadd_rn(acc[1], d0.y);
        acc[2] = __fadd_rn(acc[2], d0.z); acc[3] = __fadd_rn(acc[3], d0.w);
        acc[4] = __fadd_rn(acc[4], d1.x); acc[5] = __fadd_rn(acc[5], d1.y);
        acc[6] = __fadd_rn(acc[6], d1.z); acc[7] = __fadd_rn(acc[7], d1.w);
    }
    for (; i < kn; i++) {
        int k = klist[r][i];
        const float4* p = (const float4*)(g_w2T + (size_t)k * CDIM + c0);
        float4 v0 = p[0], v1 = p[1];
        acc[0] = __fadd_rn(acc[0], v0.x); acc[1] = __fadd_rn(acc[1], v0.y);
        acc[2] = __fadd_rn(acc[2], v0.z); acc[3] = __fadd_rn(acc[3], v0.w);
        acc[4] = __fadd_rn(acc[4], v1.x); acc[5] = __fadd_rn(acc[5], v1.y);
        acc[6] = __fadd_rn(acc[6], v1.z); acc[7] = __fadd_rn(acc[7], v1.w);
    }

    float* op = g_o2 + (size_t)row * CDIM + c0;
    *(float4*)(op)     = make_float4(acc[0], acc[1], acc[2], acc[3]);
    *(float4*)(op + 4) = make_float4(acc[4], acc[5], acc[6], acc[7]);
}

// ---------------- fused LIF2 + output transpose ----------------------------
// Per element p = i*196+j of slab tb: c = p % 512; identical LIF chain;
// out[tb*SLAB2 + j*512 + i] = spike.  Grid (7, 16, 32), block (32, 8).
__global__ __launch_bounds__(256)
void lif2t_kernel(const float* __restrict__ gamma, const float* __restrict__ beta,
                  float* __restrict__ out)
{
    __shared__ float tile[32][33];
    const int b  = blockIdx.z;          // 0..31
    const int i0 = blockIdx.y * 32;
    const int j0 = blockIdx.x * 32;
    const int x = threadIdx.x, y = threadIdx.y;

    const int j = j0 + x;
    const bool jok = (j < NSEQ);

    float v[4], gm[4], bt[4], mm[4], rr[4];
#pragma unroll
    for (int e = 0; e < 4; e++) {
        int i = i0 + y + e * 8;
        int c = (i * NSEQ + j) & (CDIM - 1);
        if (jok) {
            gm[e] = gamma[c];  bt[e] = beta[c];
            mm[e] = g_mean2[c]; rr[e] = g_rstd2[c];
        } else { gm[e] = bt[e] = mm[e] = rr[e] = 0.f; }
        v[e] = 0.f;
    }

    for (int t = 0; t < TSTEP; t++) {
        size_t base = (size_t)(t * BB + b) * SLAB2;
#pragma unroll
        for (int e = 0; e < 4; e++) {
            int i = i0 + y + e * 8;
            float xv = jok ? g_o2[base + (size_t)i * NSEQ + j] : 0.f;
            float xn = __fadd_rn(__fmul_rn(__fmul_rn(gm[e], __fsub_rn(xv, mm[e])), rr[e]), bt[e]);
            v[e] = __fadd_rn(v[e], __fmul_rn(__fsub_rn(xn, v[e]), 0.5f));
            float sp = (v[e] >= 1.0f) ? 1.0f : 0.0f;
            tile[y + e * 8][x] = sp;
            if (v[e] >= 1.0f) v[e] = 0.f;
        }
        __syncthreads();
#pragma unroll
        for (int e = 0; e < 4; e++) {
            int jj = j0 + y + e * 8;
            if (jj < NSEQ)
                out[base + (size_t)jj * CDIM + i0 + x] = tile[x][y + e * 8];
        }
        __syncthreads();
    }
}

// ---------------- launch ----------------------------------------------------
extern "C" void kernel_launch(void* const* d_in, const int* in_sizes, int n_in,
                              void* d_out, int out_size)
{
    const float* x  = (const float*)d_in[0];
    const float* w1 = (const float*)d_in[1];
    const float* g1 = (const float*)d_in[2];
    const float* b1 = (const float*)d_in[3];
    const float* w2 = (const float*)d_in[4];
    const float* g2 = (const float*)d_in[5];
    const float* b2 = (const float*)d_in[6];
    float* out = (float*)d_out;

    float *p_xT, *p_w1T, *p_w2T;
    cudaGetSymbolAddress((void**)&p_xT,  g_xT);
    cudaGetSymbolAddress((void**)&p_w1T, g_w1T);
    cudaGetSymbolAddress((void**)&p_w2T, g_w2T);

    zero_all_kernel<<<((size_t)MROWS * NWORD + 1023) / 1024, 1024>>>();

    transpose_rc_kernel<<<dim3(MROWS / 32, CDIM / 32), dim3(32, 8)>>>(x,  p_xT,  MROWS, CDIM);
    transpose_rc_kernel<<<dim3(HDIM / 32, CDIM / 32), dim3(32, 8)>>>(w1, p_w1T, HDIM, CDIM);
    transpose_rc_kernel<<<dim3(CDIM / 32, HDIM / 32), dim3(32, 8)>>>(w2, p_w2T, CDIM, HDIM);

    // Layer 1: pipelined f32x2 GEMM + fused BN1 stats -> g_h1, g_sum1/g_sq1
    sgemm1_kernel<<<dim3(HDIM / BN, MROWS / BM), 256>>>();
    bn_final_kernel<false><<<HDIM / 256, 256>>>();
    lif1_kernel<<<((size_t)BB * NSEQ * HDIM) / 256, 256>>>(g1, b1);

    // Layer 2: row-parallel sparse spike GEMM -> g_o2
    gemm2_sparse_kernel<<<MROWS / RPC, 512>>>();
    bn_stats2_kernel<<<MROWS / 128, 256>>>();
    bn_final_kernel<true><<<CDIM / 256, 256>>>();

    // Fused LIF2 + transpose -> out
    lif2t_kernel<<<dim3(7, 16, 32), dim3(32, 8)>>>(g2, b2, out);
}

// round 17
// speedup vs baseline: 1.5319x; 1.5319x over previous
#include <cuda_runtime.h>
#include <cstdint>
#include <cstddef>

// Problem constants
#define TB_   128
#define NSEQ  196
#define CDIM  512
#define HDIM  2048
#define TSTEP 4
#define BB    32
#define MROWS (TB_*NSEQ)          // 25088
#define SLAB1 (NSEQ*HDIM)         // 401408
#define SLAB2 (NSEQ*CDIM)         // 100352
#define NWORD 64                  // 2048 bits per GEMM2 row

// ---------------- scratch (device globals) ---------------------------------
__device__ float    g_h1[(size_t)MROWS*HDIM];   // GEMM1 out (tb*196+n, h)
__device__ float    g_o2[(size_t)MROWS*CDIM];   // GEMM2 out (tb*196+j, c)
__device__ uint32_t g_mask[(size_t)MROWS*NWORD]; // spike bitmask per GEMM2 row
__device__ float    g_w2T[(size_t)HDIM*CDIM];   // w2 transposed [k][c]
__device__ float    g_xT [(size_t)CDIM*MROWS];  // x transposed  [k][m]
__device__ float    g_w1T[(size_t)CDIM*HDIM];   // w1 transposed [k][h]
__device__ double   g_sum1[HDIM], g_sq1[HDIM];
__device__ double   g_sum2[CDIM], g_sq2[CDIM];
__device__ float    g_mean1[HDIM], g_rstd1[HDIM];
__device__ float    g_mean2[CDIM], g_rstd2[CDIM];

// ---------------- PTX helpers ----------------------------------------------
__device__ __forceinline__ uint32_t smem_u32(const void* p) {
    uint32_t a;
    asm("{ .reg .u64 t; cvta.to.shared.u64 t, %1; cvt.u32.u64 %0, t; }" : "=r"(a) : "l"(p));
    return a;
}
#define CP_ASYNC16(dst, src) \
    asm volatile("cp.async.cg.shared.global [%0], [%1], 16;" :: "r"(dst), "l"(src))
#define CP_COMMIT() asm volatile("cp.async.commit_group;")
#define CP_WAIT(n)  asm volatile("cp.async.wait_group %0;" :: "n"(n))

__device__ __forceinline__ void ffma2(unsigned long long &d,
                                      unsigned long long a,
                                      unsigned long long b)
{
    asm("fma.rn.f32x2 %0, %1, %2, %3;" : "=l"(d) : "l"(a), "l"(b), "l"(d));
}
__device__ __forceinline__ unsigned long long dup2(float v)
{
    unsigned long long r;
    asm("mov.b64 %0, {%1, %1};" : "=l"(r) : "f"(v));
    return r;
}

// ---------------- zero stats + mask (single kernel) -------------------------
__global__ void zero_all_kernel() {
    size_t i = (size_t)blockIdx.x * blockDim.x + threadIdx.x;
    if (i < HDIM) { g_sum1[i] = 0.0; g_sq1[i] = 0.0; }
    if (i < CDIM) { g_sum2[i] = 0.0; g_sq2[i] = 0.0; }
    if (i < (size_t)MROWS * NWORD) g_mask[i] = 0u;
}

// ---------------- generic 32x32 tile transpose: dst[c][r] = src[r][c] ------
__global__ void transpose_rc_kernel(const float* __restrict__ src,
                                    float* __restrict__ dst, int R, int C)
{
    __shared__ float t[32][33];
    int r0 = blockIdx.x * 32, c0 = blockIdx.y * 32;
    int x = threadIdx.x, y = threadIdx.y;     // block (32,8)
#pragma unroll
    for (int yy = y; yy < 32; yy += 8)
        t[yy][x] = src[(size_t)(r0 + yy) * C + c0 + x];
    __syncthreads();
#pragma unroll
    for (int yy = y; yy < 32; yy += 8)
        dst[(size_t)(c0 + yy) * R + r0 + x] = t[x][yy];
}

// ---------------- GEMM1: 3-stage cp.async ring + packed f32x2 (R14 exact) --
#define BM 128
#define BN 128
#define BK 16
#define NIT (CDIM / BK)   // 32

__global__ __launch_bounds__(256, 2)
void sgemm1_kernel()
{
    __shared__ __align__(16) float As[3][BK][BM];   // 24 KB
    __shared__ __align__(16) float Bs[3][BK][BN];   // 24 KB

    const int tid = threadIdx.x;
    const int m0 = blockIdx.y * BM;
    const int n0 = blockIdx.x * BN;
    const int tx = tid & 15;
    const int ty = tid >> 4;

    unsigned long long acc[8][4];
#pragma unroll
    for (int i = 0; i < 8; i++)
#pragma unroll
        for (int p = 0; p < 4; p++) acc[i][p] = 0ull;

    const int ck = tid >> 5;
    const int cc = (tid & 31) * 4;

    auto load_stage = [&](int s, int k0) {
#pragma unroll
        for (int i = 0; i < 2; i++) {
            int k = ck + i * 8;
            CP_ASYNC16(smem_u32(&As[s][k][cc]),
                       g_xT + (size_t)(k0 + k) * MROWS + m0 + cc);
        }
#pragma unroll
        for (int i = 0; i < 2; i++) {
            int k = ck + i * 8;
            CP_ASYNC16(smem_u32(&Bs[s][k][cc]),
                       g_w1T + (size_t)(k0 + k) * HDIM + n0 + cc);
        }
        CP_COMMIT();
    };

    load_stage(0, 0);
    load_stage(1, BK);

    for (int it = 0; it < NIT; it++) {
        const int cur = it % 3;
        if (it + 1 < NIT) CP_WAIT(1);
        else              CP_WAIT(0);
        __syncthreads();

#pragma unroll
        for (int k = 0; k < BK; k++) {
            float4 af0 = *(const float4*)&As[cur][k][ty * 8];
            float4 af1 = *(const float4*)&As[cur][k][ty * 8 + 4];
            unsigned long long a2[8];
            a2[0] = dup2(af0.x); a2[1] = dup2(af0.y);
            a2[2] = dup2(af0.z); a2[3] = dup2(af0.w);
            a2[4] = dup2(af1.x); a2[5] = dup2(af1.y);
            a2[6] = dup2(af1.z); a2[7] = dup2(af1.w);
            ulonglong2 bq0 = *(const ulonglong2*)&Bs[cur][k][tx * 8];
            ulonglong2 bq1 = *(const ulonglong2*)&Bs[cur][k][tx * 8 + 4];
            unsigned long long b2[4] = {bq0.x, bq0.y, bq1.x, bq1.y};
#pragma unroll
            for (int i = 0; i < 8; i++)
#pragma unroll
                for (int p = 0; p < 4; p++)
                    ffma2(acc[i][p], a2[i], b2[p]);
        }

        if (it + 2 < NIT)
            load_stage((it + 2) % 3, (it + 2) * BK);
    }

#pragma unroll
    for (int i = 0; i < 8; i++) {
        int r = m0 + ty * 8 + i;
        float* cr = g_h1 + (size_t)r * HDIM + n0 + tx * 8;
        ulonglong2 v0; v0.x = acc[i][0]; v0.y = acc[i][1];
        ulonglong2 v1; v1.x = acc[i][2]; v1.y = acc[i][3];
        *(ulonglong2*)(cr)     = v0;
        *(ulonglong2*)(cr + 4) = v1;
    }
}

// ---------------- BN stats / final (R14 exact) ------------------------------
template<bool SECOND>
__global__ __launch_bounds__(256)
void bn_stats_kernel()
{
    constexpr int CH  = SECOND ? CDIM : HDIM;
    constexpr int PER = CH / 256;
    const float* __restrict__ X = SECOND ? g_o2 : g_h1;
    double* __restrict__ SUM = SECOND ? g_sum2 : g_sum1;
    double* __restrict__ SQ  = SECOND ? g_sq2  : g_sq1;

    float s[PER], q[PER];
#pragma unroll
    for (int j = 0; j < PER; j++) { s[j] = 0.f; q[j] = 0.f; }
    const int c0 = threadIdx.x;
    const float* base = X + (size_t)blockIdx.x * 128 * CH;
    for (int r = 0; r < 128; r++) {
        const float* row = base + (size_t)r * CH;
#pragma unroll
        for (int j = 0; j < PER; j++) {
            float v = row[c0 + j * 256];
            s[j] += v;
            q[j] = fmaf(v, v, q[j]);
        }
    }
#pragma unroll
    for (int j = 0; j < PER; j++) {
        atomicAdd(&SUM[c0 + j * 256], (double)s[j]);
        atomicAdd(&SQ[c0 + j * 256],  (double)q[j]);
    }
}

template<bool SECOND>
__global__ void bn_final_kernel()
{
    constexpr int CH = SECOND ? CDIM : HDIM;
    const double* SUM = SECOND ? g_sum2 : g_sum1;
    const double* SQ  = SECOND ? g_sq2  : g_sq1;
    float* MEAN = SECOND ? g_mean2 : g_mean1;
    float* RSTD = SECOND ? g_rstd2 : g_rstd1;
    int c = blockIdx.x * blockDim.x + threadIdx.x;
    if (c < CH) {
        const double inv_n = 1.0 / (double)MROWS;
        double m   = SUM[c] * inv_n;
        double var = SQ[c] * inv_n - m * m;
        MEAN[c] = (float)m;
        RSTD[c] = rsqrtf((float)var + 1e-5f);
    }
}

// ---------------- LIF layer 1 -> spike bitmask (R14 exact) ------------------
__global__ __launch_bounds__(256)
void lif1_kernel(const float* __restrict__ gamma, const float* __restrict__ beta)
{
    size_t tid = (size_t)blockIdx.x * blockDim.x + threadIdx.x;
    int c = (int)(tid % HDIM);
    size_t rest = tid / HDIM;
    int n = (int)(rest % NSEQ);
    int b = (int)(rest / NSEQ);

    float m  = g_mean1[c];
    float r  = g_rstd1[c];
    float gm = gamma[c];
    float bt = beta[c];

    int f = n * HDIM + c;
    int k = f / NSEQ;
    int j = f - k * NSEQ;
    uint32_t bit  = 1u << (k & 31);
    int      word = k >> 5;

    float v = 0.f;
#pragma unroll
    for (int t = 0; t < TSTEP; t++) {
        int tb = t * BB + b;
        float x  = g_h1[((size_t)tb * NSEQ + n) * HDIM + c];
        float xn = __fadd_rn(__fmul_rn(__fmul_rn(gm, __fsub_rn(x, m)), r), bt);
        v = __fadd_rn(v, __fmul_rn(__fsub_rn(xn, v), 0.5f));
        if (v >= 1.0f) {
            atomicOr(&g_mask[(size_t)(tb * NSEQ + j) * NWORD + word], bit);
            v = 0.f;
        }
    }
}

// ---------------- sparse GEMM2: 8 rows in parallel (R14 exact) --------------
#define RPC 8
__global__ __launch_bounds__(512)
void gemm2_sparse_kernel()
{
    __shared__ uint16_t klist[RPC][HDIM];
    __shared__ int wsum[16];
    __shared__ int knum[RPC];

    const int tid = threadIdx.x;
    const int r   = tid >> 6;          // row slot 0..7
    const int w   = tid & 63;          // mask word
    const int row = blockIdx.x * RPC + r;

    uint32_t mw = g_mask[(size_t)row * NWORD + w];
    int cnt = __popc(mw);
    int incl = cnt;
#pragma unroll
    for (int d = 1; d < 32; d <<= 1) {
        int vv = __shfl_up_sync(0xffffffffu, incl, d);
        if ((tid & 31) >= d) incl += vv;
    }
    if ((tid & 31) == 31) wsum[tid >> 5] = incl;
    __syncthreads();

    int off = incl - cnt + ((w >= 32) ? wsum[r * 2] : 0);
    {
        uint32_t m2 = mw;
        int kb = w * 32;
        while (m2) {
            int b = __ffs(m2) - 1;
            m2 &= m2 - 1;
            klist[r][off++] = (uint16_t)(kb + b);
        }
    }
    if (w == 0) knum[r] = wsum[r * 2] + wsum[r * 2 + 1];
    __syncthreads();

    const int c0 = (tid & 63) * 8;
    const int kn = knum[r];
    float acc[8];
#pragma unroll
    for (int j = 0; j < 8; j++) acc[j] = 0.f;

    int i = 0;
    for (; i + 4 <= kn; i += 4) {
        int k0 = klist[r][i+0], k1 = klist[r][i+1];
        int k2 = klist[r][i+2], k3 = klist[r][i+3];
        const float4* p0 = (const float4*)(g_w2T + (size_t)k0 * CDIM + c0);
        const float4* p1 = (const float4*)(g_w2T + (size_t)k1 * CDIM + c0);
        const float4* p2 = (const float4*)(g_w2T + (size_t)k2 * CDIM + c0);
        const float4* p3 = (const float4*)(g_w2T + (size_t)k3 * CDIM + c0);
        float4 a0 = p0[0], a1 = p0[1];
        float4 b0 = p1[0], b1 = p1[1];
        float4 c0_ = p2[0], c1_ = p2[1];
        float4 d0 = p3[0], d1 = p3[1];
        acc[0] = __fadd_rn(acc[0], a0.x); acc[1] = __fadd_rn(acc[1], a0.y);
        acc[2] = __fadd_rn(acc[2], a0.z); acc[3] = __fadd_rn(acc[3], a0.w);
        acc[4] = __fadd_rn(acc[4], a1.x); acc[5] = __fadd_rn(acc[5], a1.y);
        acc[6] = __fadd_rn(acc[6], a1.z); acc[7] = __fadd_rn(acc[7], a1.w);
        acc[0] = __fadd_rn(acc[0], b0.x); acc[1] = __fadd_rn(acc[1], b0.y);
        acc[2] = __fadd_rn(acc[2], b0.z); acc[3] = __fadd_rn(acc[3], b0.w);
        acc[4] = __fadd_rn(acc[4], b1.x); acc[5] = __fadd_rn(acc[5], b1.y);
        acc[6] = __fadd_rn(acc[6], b1.z); acc[7] = __fadd_rn(acc[7], b1.w);
        acc[0] = __fadd_rn(acc[0], c0_.x); acc[1] = __fadd_rn(acc[1], c0_.y);
        acc[2] = __fadd_rn(acc[2], c0_.z); acc[3] = __fadd_rn(acc[3], c0_.w);
        acc[4] = __fadd_rn(acc[4], c1_.x); acc[5] = __fadd_rn(acc[5], c1_.y);
        acc[6] = __fadd_rn(acc[6], c1_.z); acc[7] = __fadd_rn(acc[7], c1_.w);
        acc[0] = __fadd_rn(acc[0], d0.x); acc[1] = __fadd_rn(acc[1], d0.y);
        acc[2] = __fadd_rn(acc[2], d0.z); acc[3] = __fadd_rn(acc[3], d0.w);
        acc[4] = __fadd_rn(acc[4], d1.x); acc[5] = __fadd_rn(acc[5], d1.y);
        acc[6] = __fadd_rn(acc[6], d1.z); acc[7] = __fadd_rn(acc[7], d1.w);
    }
    for (; i < kn; i++) {
        int k = klist[r][i];
        const float4* p = (const float4*)(g_w2T + (size_t)k * CDIM + c0);
        float4 v0 = p[0], v1 = p[1];
        acc[0] = __fadd_rn(acc[0], v0.x); acc[1] = __fadd_rn(acc[1], v0.y);
        acc[2] = __fadd_rn(acc[2], v0.z); acc[3] = __fadd_rn(acc[3], v0.w);
        acc[4] = __fadd_rn(acc[4], v1.x); acc[5] = __fadd_rn(acc[5], v1.y);
        acc[6] = __fadd_rn(acc[6], v1.z); acc[7] = __fadd_rn(acc[7], v1.w);
    }

    float* op = g_o2 + (size_t)row * CDIM + c0;
    *(float4*)(op)     = make_float4(acc[0], acc[1], acc[2], acc[3]);
    *(float4*)(op + 4) = make_float4(acc[4], acc[5], acc[6], acc[7]);
}

// ---------------- fused LIF2 + output transpose ----------------------------
// Per element p = i*196+j of slab tb: c = p % 512; identical LIF chain;
// out[tb*SLAB2 + j*512 + i] = spike.  Grid (7, 16, 32), block (32, 8).
__global__ __launch_bounds__(256)
void lif2t_kernel(const float* __restrict__ gamma, const float* __restrict__ beta,
                  float* __restrict__ out)
{
    __shared__ float tile[32][33];
    const int b  = blockIdx.z;          // 0..31
    const int i0 = blockIdx.y * 32;
    const int j0 = blockIdx.x * 32;
    const int x = threadIdx.x, y = threadIdx.y;

    const int j = j0 + x;
    const bool jok = (j < NSEQ);

    float v[4], gm[4], bt[4], mm[4], rr[4];
#pragma unroll
    for (int e = 0; e < 4; e++) {
        int i = i0 + y + e * 8;
        int c = (i * NSEQ + j) & (CDIM - 1);
        if (jok) {
            gm[e] = gamma[c];  bt[e] = beta[c];
            mm[e] = g_mean2[c]; rr[e] = g_rstd2[c];
        } else { gm[e] = bt[e] = mm[e] = rr[e] = 0.f; }
        v[e] = 0.f;
    }

    for (int t = 0; t < TSTEP; t++) {
        size_t base = (size_t)(t * BB + b) * SLAB2;
#pragma unroll
        for (int e = 0; e < 4; e++) {
            int i = i0 + y + e * 8;
            float xv = jok ? g_o2[base + (size_t)i * NSEQ + j] : 0.f;
            float xn = __fadd_rn(__fmul_rn(__fmul_rn(gm[e], __fsub_rn(xv, mm[e])), rr[e]), bt[e]);
            v[e] = __fadd_rn(v[e], __fmul_rn(__fsub_rn(xn, v[e]), 0.5f));
            float sp = (v[e] >= 1.0f) ? 1.0f : 0.0f;
            tile[y + e * 8][x] = sp;
            if (v[e] >= 1.0f) v[e] = 0.f;
        }
        __syncthreads();
#pragma unroll
        for (int e = 0; e < 4; e++) {
            int jj = j0 + y + e * 8;
            if (jj < NSEQ)
                out[base + (size_t)jj * CDIM + i0 + x] = tile[x][y + e * 8];
        }
        __syncthreads();
    }
}

// ---------------- launch ----------------------------------------------------
extern "C" void kernel_launch(void* const* d_in, const int* in_sizes, int n_in,
                              void* d_out, int out_size)
{
    const float* x  = (const float*)d_in[0];
    const float* w1 = (const float*)d_in[1];
    const float* g1 = (const float*)d_in[2];
    const float* b1 = (const float*)d_in[3];
    const float* w2 = (const float*)d_in[4];
    const float* g2 = (const float*)d_in[5];
    const float* b2 = (const float*)d_in[6];
    float* out = (float*)d_out;

    float *p_xT, *p_w1T, *p_w2T;
    cudaGetSymbolAddress((void**)&p_xT,  g_xT);
    cudaGetSymbolAddress((void**)&p_w1T, g_w1T);
    cudaGetSymbolAddress((void**)&p_w2T, g_w2T);

    zero_all_kernel<<<((size_t)MROWS * NWORD + 1023) / 1024, 1024>>>();

    transpose_rc_kernel<<<dim3(MROWS / 32, CDIM / 32), dim3(32, 8)>>>(x,  p_xT,  MROWS, CDIM);
    transpose_rc_kernel<<<dim3(HDIM / 32, CDIM / 32), dim3(32, 8)>>>(w1, p_w1T, HDIM, CDIM);
    transpose_rc_kernel<<<dim3(CDIM / 32, HDIM / 32), dim3(32, 8)>>>(w2, p_w2T, CDIM, HDIM);

    // Layer 1: pipelined f32x2 GEMM (R14 exact) -> g_h1
    sgemm1_kernel<<<dim3(HDIM / BN, MROWS / BM), 256>>>();
    bn_stats_kernel<false><<<MROWS / 128, 256>>>();
    bn_final_kernel<false><<<HDIM / 256, 256>>>();
    lif1_kernel<<<((size_t)BB * NSEQ * HDIM) / 256, 256>>>(g1, b1);

    // Layer 2: row-parallel sparse spike GEMM -> g_o2
    gemm2_sparse_kernel<<<MROWS / RPC, 512>>>();
    bn_stats_kernel<true><<<MROWS / 128, 256>>>();
    bn_final_kernel<true><<<CDIM / 256, 256>>>();

    // Fused LIF2 + transpose -> out
    lif2t_kernel<<<dim3(7, 16, 32), dim3(32, 8)>>>(g2, b2, out);
}